// round 16
// baseline (speedup 1.0000x reference)
#include <cuda_runtime.h>

// JPEG differentiable-round pipeline, fully fused, 128-thread CTA per 32x32 tile.
// Thread (warp w, colg, lane8) owns Y tile row 8w+lane8, cols 8*colg..+7 —
// exactly one 8x8-block row — END TO END: global load -> YCbCr -> DCT row
// stage in registers -> smem transpose (conflict-free stride-9 scratch) ->
// quant -> IDCT -> registers -> RGB -> global store. Y touches smem only for
// the two transposes (4 passes -> 2 passes vs round 6). Chroma is downsampled
// via shfl.xor(1), processed in-place in 16x17 smem planes by all 4 warps
// (2 chroma blocks per warp). DCT matrix is immediate-folded (no loads).

#define HW 512
#define PLANE (512 * 512)
#define CSTR 17   // chroma plane stride (floats)

// Orthonormal 8x8 DCT-II matrix D[u][x] = 0.5*alpha_u*cos((2x+1)u*pi/16).
__device__ constexpr float DC[64] = {
    0.35355339059327373f,  0.35355339059327373f,  0.35355339059327373f,  0.35355339059327373f,
    0.35355339059327373f,  0.35355339059327373f,  0.35355339059327373f,  0.35355339059327373f,
    0.49039264020161522f,  0.41573480615127262f,  0.27778511650980114f,  0.09754516100806417f,
   -0.09754516100806417f, -0.27778511650980114f, -0.41573480615127262f, -0.49039264020161522f,
    0.46193976625564337f,  0.19134171618254492f, -0.19134171618254492f, -0.46193976625564337f,
   -0.46193976625564337f, -0.19134171618254492f,  0.19134171618254492f,  0.46193976625564337f,
    0.41573480615127262f, -0.09754516100806417f, -0.49039264020161522f, -0.27778511650980114f,
    0.27778511650980114f,  0.49039264020161522f,  0.09754516100806417f, -0.41573480615127262f,
    0.35355339059327373f, -0.35355339059327373f, -0.35355339059327373f,  0.35355339059327373f,
    0.35355339059327373f, -0.35355339059327373f, -0.35355339059327373f,  0.35355339059327373f,
    0.27778511650980114f, -0.49039264020161522f,  0.09754516100806417f,  0.41573480615127262f,
   -0.41573480615127262f, -0.09754516100806417f,  0.49039264020161522f, -0.27778511650980114f,
    0.19134171618254492f, -0.46193976625564337f,  0.46193976625564337f, -0.19134171618254492f,
   -0.19134171618254492f,  0.46193976625564337f, -0.46193976625564337f,  0.19134171618254492f,
    0.09754516100806417f, -0.27778511650980114f,  0.41573480615127262f, -0.49039264020161522f,
    0.49039264020161522f, -0.41573480615127262f,  0.27778511650980114f, -0.09754516100806417f};

__constant__ int YTAB[64] = {
    16, 11, 10, 16, 24, 40, 51, 61,
    12, 12, 14, 19, 26, 58, 60, 55,
    14, 13, 16, 24, 40, 57, 69, 56,
    14, 17, 22, 29, 51, 87, 80, 62,
    18, 22, 37, 56, 68, 109, 103, 77,
    24, 35, 55, 64, 81, 104, 113, 92,
    49, 64, 78, 87, 103, 121, 120, 101,
    72, 92, 95, 98, 112, 100, 103, 99};

__constant__ int CTAB[64] = {
    17, 18, 24, 47, 99, 99, 99, 99,
    18, 21, 26, 66, 99, 99, 99, 99,
    24, 26, 56, 99, 99, 99, 99, 99,
    47, 66, 99, 99, 99, 99, 99, 99,
    99, 99, 99, 99, 99, 99, 99, 99,
    99, 99, 99, 99, 99, 99, 99, 99,
    99, 99, 99, 99, 99, 99, 99, 99,
    99, 99, 99, 99, 99, 99, 99, 99};

// QUALITY = 80 -> FACTOR = 0.4
#define QFACTOR 0.4f

__global__ void __launch_bounds__(128)
jpeg_kernel(const float* __restrict__ in, float* __restrict__ out)
{
    // Y transpose scratch: 4 warps x 4 blocks x (8 rows x stride 9) floats.
    // Bank-conflict-free: row ops hit banks (8*colg + 9*lane8 + i) mod 32,
    // column ops hit banks (8*colg + lane8) — both permutations.
    __shared__ float ysc[4 * 4 * 72];
    __shared__ float cbs[16 * CSTR];   // downsampled Cb plane
    __shared__ float crs[16 * CSTR];   // downsampled Cr plane
    __shared__ float2 qpY[64], qpC[64];  // {q, 1/q}

    const int tid   = threadIdx.x;
    const int w     = tid >> 5;        // warp 0..3
    const int t5    = tid & 31;
    const int colg  = t5 >> 3;         // block column group 0..3
    const int lane8 = t5 & 7;          // row within 8x8 block

    if (tid < 64) {
        float qy = (float)YTAB[tid] * QFACTOR;
        float qc = (float)CTAB[tid] * QFACTOR;
        qpY[tid] = make_float2(qy, 1.0f / qy);
        qpC[tid] = make_float2(qc, 1.0f / qc);
    }

    // ---- phase A: load own 8 pixels x 3 planes, YCbCr, chroma downsample ----
    const int b   = blockIdx.z;
    const int gy0 = blockIdx.y * 32;
    const int gx0 = blockIdx.x * 32;

    const float* pR = in + (size_t)b * 3 * PLANE;
    const float* pG = pR + PLANE;
    const float* pB = pG + PLANE;
    const size_t off = (size_t)(gy0 + 8 * w + lane8) * HW + gx0 + 8 * colg;

    float4 r0 = __ldcs((const float4*)(pR + off));
    float4 r1 = __ldcs((const float4*)(pR + off + 4));
    float4 g0 = __ldcs((const float4*)(pG + off));
    float4 g1 = __ldcs((const float4*)(pG + off + 4));
    float4 b0 = __ldcs((const float4*)(pB + off));
    float4 b1 = __ldcs((const float4*)(pB + off + 4));

    float yv[8], cbv[8], crv[8];
    #pragma unroll
    for (int i = 0; i < 8; i++) {
        float R = (i < 4 ? (&r0.x)[i] : (&r1.x)[i - 4]) * 255.0f;
        float G = (i < 4 ? (&g0.x)[i] : (&g1.x)[i - 4]) * 255.0f;
        float B = (i < 4 ? (&b0.x)[i] : (&b1.x)[i - 4]) * 255.0f;
        yv[i]  =  0.299f    * R + 0.587f    * G + 0.114f    * B;
        cbv[i] = -0.168736f * R - 0.331264f * G + 0.5f      * B + 128.0f;
        crv[i] =  0.5f      * R - 0.418688f * G - 0.081312f * B + 128.0f;
    }

    // chroma 2x2 mean: horizontal pairs in regs, vertical with lane^1 partner
    // (row pairs (2k,2k+1) are lanes 2k,2k+1 of the same colg).
    {
        float hb[4], hr[4];
        #pragma unroll
        for (int j = 0; j < 4; j++) {
            hb[j] = cbv[2 * j] + cbv[2 * j + 1];
            hr[j] = crv[2 * j] + crv[2 * j + 1];
        }
        float vb[4], vr[4];
        #pragma unroll
        for (int j = 0; j < 4; j++) {
            vb[j] = hb[j] + __shfl_xor_sync(0xffffffffu, hb[j], 1);
            vr[j] = hr[j] + __shfl_xor_sync(0xffffffffu, hr[j], 1);
        }
        if ((lane8 & 1) == 0) {
            int crow = 4 * w + (lane8 >> 1);      // 0..15
            int cbase = crow * CSTR + 4 * colg;
            #pragma unroll
            for (int j = 0; j < 4; j++) {
                cbs[cbase + j] = 0.25f * vb[j];
                crs[cbase + j] = 0.25f * vr[j];
            }
        }
    }
    __syncthreads();   // chroma planes complete (cross-warp consumers next)

    // ---- Y phase C: DCT -> quant -> IDCT; only transposes touch smem ----
    float yout[8];
    {
        float* base = ysc + w * 288 + colg * 72;   // this block's scratch

        // stage 1 (register-only): G[lane8][v] = sum_y (yv[y]-128)*D[v][y]
        float g[8];
        #pragma unroll
        for (int v = 0; v < 8; v++) {
            float s = 0.0f;
            #pragma unroll
            for (int y = 0; y < 8; y++) s += (yv[y] - 128.0f) * DC[v * 8 + y];
            g[v] = s;
        }
        #pragma unroll
        for (int v = 0; v < 8; v++) base[lane8 * 9 + v] = g[v];  // own row
        __syncwarp();

        // stage 2: thread owns column v=lane8
        float gc[8];
        #pragma unroll
        for (int k = 0; k < 8; k++) gc[k] = base[k * 9 + lane8];
        float c[8];
        #pragma unroll
        for (int u = 0; u < 8; u++) {
            float s = 0.0f;
            #pragma unroll
            for (int k = 0; k < 8; k++) s += gc[k] * DC[u * 8 + k];
            c[u] = s;
        }
        // quant (column lane8 of the table)
        #pragma unroll
        for (int u = 0; u < 8; u++) {
            float2 qq = qpY[u * 8 + lane8];
            float cf = c[u] * qq.y;
            float r  = rintf(cf);
            float d  = cf - r;
            c[u] = (r + d * d * d) * qq.x;
        }
        // stage 3 (registers): T[x][lane8] = sum_u c[u]*D[u][x]
        #pragma unroll
        for (int x = 0; x < 8; x++) {
            float s = 0.0f;
            #pragma unroll
            for (int u = 0; u < 8; u++) s += c[u] * DC[u * 8 + x];
            gc[x] = s;
        }
        #pragma unroll
        for (int x = 0; x < 8; x++) base[x * 9 + lane8] = gc[x];  // own column
        __syncwarp();

        // stage 4: thread owns row lane8; result stays in registers
        float tr[8];
        #pragma unroll
        for (int v = 0; v < 8; v++) tr[v] = base[lane8 * 9 + v];
        #pragma unroll
        for (int y = 0; y < 8; y++) {
            float s = 128.0f;
            #pragma unroll
            for (int v = 0; v < 8; v++) s += tr[v] * DC[v * 8 + y];
            yout[y] = s;
        }
    }

    // ---- chroma phase C: 8 chroma blocks over 4 warps (2 blocks/warp) ----
    // warp w: plane = w>>1 (0=Cb,1=Cr), blocks (w&1)*2 + {0,1}; 16 active lanes.
    {
        const int blkh = t5 >> 3;          // 0..3; active if <2
        const bool act = blkh < 2;
        float* plane = (w >> 1) ? crs : cbs;
        const int blk2 = (w & 1) * 2 + blkh;
        float* base = plane + (blk2 >> 1) * 8 * CSTR + (blk2 & 1) * 8;

        float g[8], c[8];
        if (act) {
            float xr[8];
            #pragma unroll
            for (int y = 0; y < 8; y++) xr[y] = base[lane8 * CSTR + y] - 128.0f;
            #pragma unroll
            for (int v = 0; v < 8; v++) {
                float s = 0.0f;
                #pragma unroll
                for (int y = 0; y < 8; y++) s += xr[y] * DC[v * 8 + y];
                g[v] = s;
            }
            #pragma unroll
            for (int v = 0; v < 8; v++) base[lane8 * CSTR + v] = g[v];
        }
        __syncwarp();
        if (act) {
            float gc[8];
            #pragma unroll
            for (int k = 0; k < 8; k++) gc[k] = base[k * CSTR + lane8];
            #pragma unroll
            for (int u = 0; u < 8; u++) {
                float s = 0.0f;
                #pragma unroll
                for (int k = 0; k < 8; k++) s += gc[k] * DC[u * 8 + k];
                c[u] = s;
            }
            #pragma unroll
            for (int u = 0; u < 8; u++) {
                float2 qq = qpC[u * 8 + lane8];
                float cf = c[u] * qq.y;
                float r  = rintf(cf);
                float d  = cf - r;
                c[u] = (r + d * d * d) * qq.x;
            }
            #pragma unroll
            for (int x = 0; x < 8; x++) {
                float s = 0.0f;
                #pragma unroll
                for (int u = 0; u < 8; u++) s += c[u] * DC[u * 8 + x];
                g[x] = s;
            }
            #pragma unroll
            for (int x = 0; x < 8; x++) base[x * CSTR + lane8] = g[x];  // own col
        }
        __syncwarp();
        if (act) {
            float tr[8];
            #pragma unroll
            for (int v = 0; v < 8; v++) tr[v] = base[lane8 * CSTR + v];
            #pragma unroll
            for (int y = 0; y < 8; y++) {
                float s = 128.0f;
                #pragma unroll
                for (int v = 0; v < 8; v++) s += tr[v] * DC[v * 8 + y];
                base[lane8 * CSTR + y] = s;   // own row
            }
        }
    }
    __syncthreads();   // chroma results visible to all warps

    // ---- phase D: upsample chroma, YCbCr->RGB, clip, store own row ----
    {
        const int crow = 4 * w + (lane8 >> 1);
        const int cbase = crow * CSTR + 4 * colg;
        float4 ro0, ro1, go0, go1, bo0, bo1;
        #pragma unroll
        for (int j = 0; j < 4; j++) {
            float cb = cbs[cbase + j] - 128.0f;
            float cr = crs[cbase + j] - 128.0f;
            #pragma unroll
            for (int h = 0; h < 2; h++) {
                int p = 2 * j + h;
                float y = yout[p];
                float R = y + 1.402f * cr;
                float G = y - 0.344136f * cb - 0.714136f * cr;
                float B = y + 1.772f * cb;
                R = fminf(fmaxf(R, 0.0f), 255.0f) * (1.0f / 255.0f);
                G = fminf(fmaxf(G, 0.0f), 255.0f) * (1.0f / 255.0f);
                B = fminf(fmaxf(B, 0.0f), 255.0f) * (1.0f / 255.0f);
                if (p < 4) { (&ro0.x)[p] = R; (&go0.x)[p] = G; (&bo0.x)[p] = B; }
                else       { (&ro1.x)[p-4] = R; (&go1.x)[p-4] = G; (&bo1.x)[p-4] = B; }
            }
        }
        float* oR = out + (size_t)b * 3 * PLANE;
        float* oG = oR + PLANE;
        float* oB = oG + PLANE;
        __stcs((float4*)(oR + off),     ro0);
        __stcs((float4*)(oR + off + 4), ro1);
        __stcs((float4*)(oG + off),     go0);
        __stcs((float4*)(oG + off + 4), go1);
        __stcs((float4*)(oB + off),     bo0);
        __stcs((float4*)(oB + off + 4), bo1);
    }
}

extern "C" void kernel_launch(void* const* d_in, const int* in_sizes, int n_in,
                              void* d_out, int out_size)
{
    const float* in = (const float*)d_in[0];
    float* out = (float*)d_out;
    dim3 grid(HW / 32, HW / 32, 32);   // (16, 16, 32) tiles
    jpeg_kernel<<<grid, 128>>>(in, out);
}